// round 2
// baseline (speedup 1.0000x reference)
#include <cuda_runtime.h>

// Problem: B=1024, F=64, D=64
//   layer: h_new[o,d] = relu(b[o] + sum_{i,j} W[o, i*64+j] * x[i,d] * h[j,d])
//   (two layers; h0 = x; x stays the original input for both layers)
//   out[b] = bfc + sum_{o,d} Wfc[o]      * h1[o,d]
//                + sum_{o,d} Wfc[64+o]   * h2[o,d]
//
// Strategy: 1 CTA per batch. Per layer, loop i = 0..63:
//   G = W_i @ h   (64x64x64 GEMM, W_i/h in SMEM, 4x4 register tiles)
//   acc[o,d] += x[i,d] * G[o,d]
// d-dimension packed into f32x2 pairs -> fma.rn.f32x2 for full fp32 rate.

__device__ __forceinline__ void ffma2(unsigned long long &d,
                                      unsigned long long a,
                                      unsigned long long b) {
    asm("fma.rn.f32x2 %0, %1, %2, %0;" : "+l"(d) : "l"(a), "l"(b));
}
__device__ __forceinline__ unsigned long long splat2(float w) {
    unsigned long long r;
    asm("mov.b64 %0, {%1, %1};" : "=l"(r) : "f"(w));
    return r;
}
__device__ __forceinline__ void unpack2(unsigned long long v, float &lo, float &hi) {
    asm("mov.b64 {%0, %1}, %2;" : "=f"(lo), "=f"(hi) : "l"(v));
}

__global__ __launch_bounds__(256, 1) void CIN_52553219834054_kernel(
    const float* __restrict__ x,
    const float* __restrict__ W1, const float* __restrict__ b1,
    const float* __restrict__ W2, const float* __restrict__ b2,
    const float* __restrict__ Wfc, const float* __restrict__ bfc,
    float* __restrict__ out)
{
    __shared__ __align__(16) float x_s[64 * 64];  // x[i][d]
    __shared__ __align__(16) float h_s[64 * 64];  // h[j][d]
    __shared__ __align__(16) float w_s[64 * 64];  // W chunk: [o][j] for current i

    const int tid   = threadIdx.x;
    const int tx    = tid & 15;        // d-tile index
    const int ty    = tid >> 4;        // o-tile index
    const int obase = ty * 4;
    const int dbase = tx * 4;
    const int bidx  = blockIdx.x;

    // ---- load x into x_s and h_s (h starts as x) ----
    {
        const float4* xg = reinterpret_cast<const float4*>(x + (size_t)bidx * 4096);
        float4* xs4 = reinterpret_cast<float4*>(x_s);
        float4* hs4 = reinterpret_cast<float4*>(h_s);
        #pragma unroll
        for (int t = 0; t < 4; ++t) {
            float4 v = xg[tid + 256 * t];
            xs4[tid + 256 * t] = v;
            hs4[tid + 256 * t] = v;
        }
    }

    // ---- W-chunk prefetch address map (4 float4 per thread per i) ----
    // chunk layout in w_s: [o][j], row stride 64 floats.
    int goff[4], soff[4];
    #pragma unroll
    for (int t = 0; t < 4; ++t) {
        int q  = tid + 256 * t;     // 0..1023 float4 slots
        int oq = q >> 4;            // 0..63
        int j4 = (q & 15) * 4;      // 0..60
        goff[t] = oq * 4096 + j4;   // + i*64 per step
        soff[t] = oq * 64 + j4;
    }

    float pool = 0.0f;

    #pragma unroll 1
    for (int l = 0; l < 2; ++l) {
        const float* __restrict__ Wg = (l == 0) ? W1 : W2;
        const float* __restrict__ bg = (l == 0) ? b1 : b2;

        // acc[o,d] initialized to bias[o], packed f32x2 over d
        unsigned long long acc[4][2];
        #pragma unroll
        for (int a = 0; a < 4; ++a) {
            unsigned long long bb = splat2(bg[obase + a]);
            acc[a][0] = bb;
            acc[a][1] = bb;
        }

        // prefetch chunk i = 0
        float4 pre[4];
        #pragma unroll
        for (int t = 0; t < 4; ++t)
            pre[t] = *reinterpret_cast<const float4*>(Wg + goff[t]);

        __syncthreads();   // (A) prior consumers of w_s / producers of h_s done
        #pragma unroll
        for (int t = 0; t < 4; ++t)
            *reinterpret_cast<float4*>(&w_s[soff[t]]) = pre[t];

        for (int i = 0; i < 64; ++i) {
            __syncthreads();   // (B) w_s chunk i visible

            if (i < 63) {
                #pragma unroll
                for (int t = 0; t < 4; ++t)
                    pre[t] = *reinterpret_cast<const float4*>(Wg + goff[t] + (i + 1) * 64);
            }

            const ulonglong2 xv =
                *reinterpret_cast<const ulonglong2*>(&x_s[i * 64 + dbase]);

            unsigned long long G[4][2];
            #pragma unroll
            for (int a = 0; a < 4; ++a) { G[a][0] = 0ull; G[a][1] = 0ull; }

            const float* w0r = &w_s[(obase + 0) * 64];
            const float* w1r = &w_s[(obase + 1) * 64];
            const float* w2r = &w_s[(obase + 2) * 64];
            const float* w3r = &w_s[(obase + 3) * 64];

            #pragma unroll 4
            for (int j = 0; j < 64; j += 4) {
                float q0[4], q1[4], q2[4], q3[4];
                *reinterpret_cast<float4*>(q0) = *reinterpret_cast<const float4*>(w0r + j);
                *reinterpret_cast<float4*>(q1) = *reinterpret_cast<const float4*>(w1r + j);
                *reinterpret_cast<float4*>(q2) = *reinterpret_cast<const float4*>(w2r + j);
                *reinterpret_cast<float4*>(q3) = *reinterpret_cast<const float4*>(w3r + j);
                #pragma unroll
                for (int jj = 0; jj < 4; ++jj) {
                    const ulonglong2 hv = *reinterpret_cast<const ulonglong2*>(
                        &h_s[(j + jj) * 64 + dbase]);
                    const unsigned long long s0 = splat2(q0[jj]);
                    const unsigned long long s1 = splat2(q1[jj]);
                    const unsigned long long s2 = splat2(q2[jj]);
                    const unsigned long long s3 = splat2(q3[jj]);
                    ffma2(G[0][0], s0, hv.x); ffma2(G[0][1], s0, hv.y);
                    ffma2(G[1][0], s1, hv.x); ffma2(G[1][1], s1, hv.y);
                    ffma2(G[2][0], s2, hv.x); ffma2(G[2][1], s2, hv.y);
                    ffma2(G[3][0], s3, hv.x); ffma2(G[3][1], s3, hv.y);
                }
            }

            // acc += x[i,d] * G
            #pragma unroll
            for (int a = 0; a < 4; ++a) {
                ffma2(acc[a][0], xv.x, G[a][0]);
                ffma2(acc[a][1], xv.y, G[a][1]);
            }

            __syncthreads();   // (C) chunk i fully consumed
            if (i < 63) {
                #pragma unroll
                for (int t = 0; t < 4; ++t)
                    *reinterpret_cast<float4*>(&w_s[soff[t]]) = pre[t];
            }
        }

        // ---- epilogue: relu, write h (layer 0 only), weighted pool ----
        #pragma unroll
        for (int a = 0; a < 4; ++a) {
            const float wfc = Wfc[l * 64 + obase + a];
            #pragma unroll
            for (int p = 0; p < 2; ++p) {
                float lo, hi;
                unpack2(acc[a][p], lo, hi);
                lo = fmaxf(lo, 0.0f);
                hi = fmaxf(hi, 0.0f);
                if (l == 0) {
                    h_s[(obase + a) * 64 + dbase + 2 * p]     = lo;
                    h_s[(obase + a) * 64 + dbase + 2 * p + 1] = hi;
                }
                pool += wfc * (lo + hi);
            }
        }
        // loop re-entry does __syncthreads() at (A) before anyone touches h_s/w_s
    }

    // ---- block-wide reduction of pool; w_s is free, reuse first 8 slots ----
    #pragma unroll
    for (int off = 16; off > 0; off >>= 1)
        pool += __shfl_down_sync(0xffffffffu, pool, off);
    if ((tid & 31) == 0) w_s[tid >> 5] = pool;
    __syncthreads();
    if (tid == 0) {
        float s = 0.0f;
        #pragma unroll
        for (int w = 0; w < 8; ++w) s += w_s[w];
        out[bidx] = s + bfc[0];
    }
}

extern "C" void kernel_launch(void* const* d_in, const int* in_sizes, int n_in,
                              void* d_out, int out_size) {
    const float* x   = (const float*)d_in[0];
    const float* W1  = (const float*)d_in[1];
    const float* b1  = (const float*)d_in[2];
    const float* W2  = (const float*)d_in[3];
    const float* b2  = (const float*)d_in[4];
    const float* Wfc = (const float*)d_in[5];
    const float* bfc = (const float*)d_in[6];
    CIN_52553219834054_kernel<<<1024, 256>>>(x, W1, b1, W2, b2, Wfc, bfc,
                                             (float*)d_out);
}

// round 3
// speedup vs baseline: 1.6381x; 1.6381x over previous
#include <cuda_runtime.h>

// Problem: B=1024, F=64, D=64
//   layer: h_new[o,d] = relu(b[o] + sum_{i,j} W[o, i*64+j] * x[i,d] * h[j,d])
//   (two layers; h0 = x; x stays the original input for both layers)
//   out[b] = bfc + sum_{o,d} Wfc[o]      * h1[o,d]
//                + sum_{o,d} Wfc[64+o]   * h2[o,d]
//
// Strategy: 1 CTA per batch. Per layer, loop i = 0..63:
//   G = W_i @ h   (64x64x64 GEMM, W_i/h in SMEM, 4x4 register tiles)
//   acc[o,d] += x[i,d] * G[o,d]
// d-dimension packed into f32x2 pairs -> fma.rn.f32x2 for full fp32 rate.

__device__ __forceinline__ void ffma2(unsigned long long &d,
                                      unsigned long long a,
                                      unsigned long long b) {
    asm("fma.rn.f32x2 %0, %1, %2, %0;" : "+l"(d) : "l"(a), "l"(b));
}
__device__ __forceinline__ unsigned long long splat2(float w) {
    unsigned long long r;
    asm("mov.b64 %0, {%1, %1};" : "=l"(r) : "f"(w));
    return r;
}
__device__ __forceinline__ void unpack2(unsigned long long v, float &lo, float &hi) {
    asm("mov.b64 {%0, %1}, %2;" : "=f"(lo), "=f"(hi) : "l"(v));
}

__global__ __launch_bounds__(256, 1) void CIN_52553219834054_kernel(
    const float* __restrict__ x,
    const float* __restrict__ W1, const float* __restrict__ b1,
    const float* __restrict__ W2, const float* __restrict__ b2,
    const float* __restrict__ Wfc, const float* __restrict__ bfc,
    float* __restrict__ out)
{
    __shared__ __align__(16) float x_s[64 * 64];  // x[i][d]
    __shared__ __align__(16) float h_s[64 * 64];  // h[j][d]
    __shared__ __align__(16) float w_s[64 * 64];  // W chunk: [o][j] for current i

    const int tid   = threadIdx.x;
    const int tx    = tid & 15;        // d-tile index
    const int ty    = tid >> 4;        // o-tile index
    const int obase = ty * 4;
    const int dbase = tx * 4;
    const int bidx  = blockIdx.x;

    // ---- load x into x_s and h_s (h starts as x) ----
    {
        const float4* xg = reinterpret_cast<const float4*>(x + (size_t)bidx * 4096);
        float4* xs4 = reinterpret_cast<float4*>(x_s);
        float4* hs4 = reinterpret_cast<float4*>(h_s);
        #pragma unroll
        for (int t = 0; t < 4; ++t) {
            float4 v = xg[tid + 256 * t];
            xs4[tid + 256 * t] = v;
            hs4[tid + 256 * t] = v;
        }
    }

    // ---- W-chunk prefetch address map (4 float4 per thread per i) ----
    // chunk layout in w_s: [o][j], row stride 64 floats.
    int goff[4], soff[4];
    #pragma unroll
    for (int t = 0; t < 4; ++t) {
        int q  = tid + 256 * t;     // 0..1023 float4 slots
        int oq = q >> 4;            // 0..63
        int j4 = (q & 15) * 4;      // 0..60
        goff[t] = oq * 4096 + j4;   // + i*64 per step
        soff[t] = oq * 64 + j4;
    }

    float pool = 0.0f;

    #pragma unroll 1
    for (int l = 0; l < 2; ++l) {
        const float* __restrict__ Wg = (l == 0) ? W1 : W2;
        const float* __restrict__ bg = (l == 0) ? b1 : b2;

        // acc[o,d] initialized to bias[o], packed f32x2 over d
        unsigned long long acc[4][2];
        #pragma unroll
        for (int a = 0; a < 4; ++a) {
            unsigned long long bb = splat2(bg[obase + a]);
            acc[a][0] = bb;
            acc[a][1] = bb;
        }

        // prefetch chunk i = 0
        float4 pre[4];
        #pragma unroll
        for (int t = 0; t < 4; ++t)
            pre[t] = *reinterpret_cast<const float4*>(Wg + goff[t]);

        __syncthreads();   // (A) prior consumers of w_s / producers of h_s done
        #pragma unroll
        for (int t = 0; t < 4; ++t)
            *reinterpret_cast<float4*>(&w_s[soff[t]]) = pre[t];

        for (int i = 0; i < 64; ++i) {
            __syncthreads();   // (B) w_s chunk i visible

            if (i < 63) {
                #pragma unroll
                for (int t = 0; t < 4; ++t)
                    pre[t] = *reinterpret_cast<const float4*>(Wg + goff[t] + (i + 1) * 64);
            }

            const ulonglong2 xv =
                *reinterpret_cast<const ulonglong2*>(&x_s[i * 64 + dbase]);

            unsigned long long G[4][2];
            #pragma unroll
            for (int a = 0; a < 4; ++a) { G[a][0] = 0ull; G[a][1] = 0ull; }

            const float* w0r = &w_s[(obase + 0) * 64];
            const float* w1r = &w_s[(obase + 1) * 64];
            const float* w2r = &w_s[(obase + 2) * 64];
            const float* w3r = &w_s[(obase + 3) * 64];

            #pragma unroll 4
            for (int j = 0; j < 64; j += 4) {
                float q0[4], q1[4], q2[4], q3[4];
                *reinterpret_cast<float4*>(q0) = *reinterpret_cast<const float4*>(w0r + j);
                *reinterpret_cast<float4*>(q1) = *reinterpret_cast<const float4*>(w1r + j);
                *reinterpret_cast<float4*>(q2) = *reinterpret_cast<const float4*>(w2r + j);
                *reinterpret_cast<float4*>(q3) = *reinterpret_cast<const float4*>(w3r + j);
                #pragma unroll
                for (int jj = 0; jj < 4; ++jj) {
                    const ulonglong2 hv = *reinterpret_cast<const ulonglong2*>(
                        &h_s[(j + jj) * 64 + dbase]);
                    const unsigned long long s0 = splat2(q0[jj]);
                    const unsigned long long s1 = splat2(q1[jj]);
                    const unsigned long long s2 = splat2(q2[jj]);
                    const unsigned long long s3 = splat2(q3[jj]);
                    ffma2(G[0][0], s0, hv.x); ffma2(G[0][1], s0, hv.y);
                    ffma2(G[1][0], s1, hv.x); ffma2(G[1][1], s1, hv.y);
                    ffma2(G[2][0], s2, hv.x); ffma2(G[2][1], s2, hv.y);
                    ffma2(G[3][0], s3, hv.x); ffma2(G[3][1], s3, hv.y);
                }
            }

            // acc += x[i,d] * G
            #pragma unroll
            for (int a = 0; a < 4; ++a) {
                ffma2(acc[a][0], xv.x, G[a][0]);
                ffma2(acc[a][1], xv.y, G[a][1]);
            }

            __syncthreads();   // (C) chunk i fully consumed
            if (i < 63) {
                #pragma unroll
                for (int t = 0; t < 4; ++t)
                    *reinterpret_cast<float4*>(&w_s[soff[t]]) = pre[t];
            }
        }

        // ---- epilogue: relu, write h (layer 0 only), weighted pool ----
        #pragma unroll
        for (int a = 0; a < 4; ++a) {
            const float wfc = Wfc[l * 64 + obase + a];
            #pragma unroll
            for (int p = 0; p < 2; ++p) {
                float lo, hi;
                unpack2(acc[a][p], lo, hi);
                lo = fmaxf(lo, 0.0f);
                hi = fmaxf(hi, 0.0f);
                if (l == 0) {
                    h_s[(obase + a) * 64 + dbase + 2 * p]     = lo;
                    h_s[(obase + a) * 64 + dbase + 2 * p + 1] = hi;
                }
                pool += wfc * (lo + hi);
            }
        }
        // loop re-entry does __syncthreads() at (A) before anyone touches h_s/w_s
    }

    // ---- block-wide reduction of pool; w_s is free, reuse first 8 slots ----
    #pragma unroll
    for (int off = 16; off > 0; off >>= 1)
        pool += __shfl_down_sync(0xffffffffu, pool, off);
    if ((tid & 31) == 0) w_s[tid >> 5] = pool;
    __syncthreads();
    if (tid == 0) {
        float s = 0.0f;
        #pragma unroll
        for (int w = 0; w < 8; ++w) s += w_s[w];
        out[bidx] = s + bfc[0];
    }
}

extern "C" void kernel_launch(void* const* d_in, const int* in_sizes, int n_in,
                              void* d_out, int out_size) {
    const float* x   = (const float*)d_in[0];
    const float* W1  = (const float*)d_in[1];
    const float* b1  = (const float*)d_in[2];
    const float* W2  = (const float*)d_in[3];
    const float* b2  = (const float*)d_in[4];
    const float* Wfc = (const float*)d_in[5];
    const float* bfc = (const float*)d_in[6];
    CIN_52553219834054_kernel<<<1024, 256>>>(x, W1, b1, W2, b2, Wfc, bfc,
                                             (float*)d_out);
}

// round 5
// speedup vs baseline: 3.7054x; 2.2620x over previous
#include <cuda_runtime.h>
#include <cuda_bf16.h>
#include <stdint.h>

// ============================================================================
// B=1024, F=64, D=64.
//   layer: h'[o,d] = relu(b[o] + sum_{i,j} W[o,i*64+j] * x[i,d] * h[j,d])
//   out[b] = bfc + sum_o Wfc[o]*sum_d h1 + sum_o Wfc[64+o]*sum_d h2
//
// Warp-level HMMA (mma.sync m16n8k16 bf16->f32), baseline PTX (no sm_103a
// features). Per CTA: 2 batches. Per layer, per batch:
//   D(64x64) = sum_i  W_i(64x64[j]) @ z_i(64[j] x 64[d]),
//   z_i[j][d] = x[i,d] * h[j,d]   (generated on the fly into smem)
// bf16x3 split: D += Wh*Zh + Wh*Zl + Wl*Zh  (fp32 accum in registers).
// Rows padded to 144B -> conflict-free ldmatrix without swizzle.
// ============================================================================

#define WS_OFF   0            // W tiles: 2 stages x (hi 9216 + lo 9216)
#define ZS_OFF   36864        // z: 2 batches x 2 stages x (hi 9216 + lo 9216)
#define XS_OFF   110592       // x fp32 [b][i*68+d]
#define HS_OFF   145408       // h fp32 [b][j*68+d]
#define POOL_OFF 180224
#define SMEM_TOTAL 180288

// Pre-split, pre-padded W tiles: [l][i][half][o*72 + j] bf16 (j pads zeroed)
__device__ __align__(16) __nv_bfloat16 g_Wt[2][64][2][64 * 72];

// ---------------------------------------------------------------------------
static __device__ __forceinline__ uint32_t s2u(const void* p) {
    uint32_t a;
    asm("{ .reg .u64 t; cvta.to.shared.u64 t, %1; cvt.u32.u64 %0, t; }"
        : "=r"(a) : "l"(p));
    return a;
}
static __device__ __forceinline__ void cpa16(uint32_t dst, const void* src) {
    asm volatile("cp.async.cg.shared.global [%0], [%1], 16;"
                 :: "r"(dst), "l"(src) : "memory");
}
static __device__ __forceinline__ uint32_t packbf2(float hi_el, float lo_el) {
    uint32_t r;   // [31:16]=bf16(hi_el), [15:0]=bf16(lo_el)
    asm("cvt.rn.bf16x2.f32 %0, %1, %2;" : "=r"(r) : "f"(hi_el), "f"(lo_el));
    return r;
}

#define LDSM4(r, addr) \
    asm volatile("ldmatrix.sync.aligned.m8n8.x4.shared.b16 {%0,%1,%2,%3}, [%4];" \
                 : "=r"((r)[0]), "=r"((r)[1]), "=r"((r)[2]), "=r"((r)[3]) \
                 : "r"(addr))
#define LDSM4T(r, addr) \
    asm volatile("ldmatrix.sync.aligned.m8n8.x4.trans.shared.b16 {%0,%1,%2,%3}, [%4];" \
                 : "=r"((r)[0]), "=r"((r)[1]), "=r"((r)[2]), "=r"((r)[3]) \
                 : "r"(addr))
#define MMA(c, a, b0, b1) \
    asm volatile("mma.sync.aligned.m16n8k16.row.col.f32.bf16.bf16.f32 " \
                 "{%0,%1,%2,%3},{%4,%5,%6,%7},{%8,%9},{%0,%1,%2,%3};" \
                 : "+f"((c)[0]), "+f"((c)[1]), "+f"((c)[2]), "+f"((c)[3]) \
                 : "r"((a)[0]), "r"((a)[1]), "r"((a)[2]), "r"((a)[3]), \
                   "r"(b0), "r"(b1))

// ---------------------------------------------------------------------------
// Prologue: split W into bf16 hi/lo, padded rows of 72 bf16 (pads zeroed).
__global__ void CIN_52553219834054_wsplit(const float* __restrict__ W1,
                                          const float* __restrict__ W2) {
    int idx = blockIdx.x * 256 + threadIdx.x;       // < 2*64*64*36 = 294912
    int l  = idx / 147456; int r  = idx - l * 147456;
    int i  = r / 2304;     int r2 = r - i * 2304;
    int o  = r2 / 36;      int jp = r2 - o * 36;
    int j  = jp * 2;
    uint32_t* dH = (uint32_t*)&g_Wt[l][i][0][o * 72 + j];
    uint32_t* dL = (uint32_t*)&g_Wt[l][i][1][o * 72 + j];
    if (j < 64) {
        const float* W = l ? W2 : W1;
        const float* p = W + o * 4096 + i * 64 + j;
        float v0 = p[0], v1 = p[1];
        uint32_t hp = packbf2(v1, v0);
        float r0 = v0 - __uint_as_float(hp << 16);
        float r1 = v1 - __uint_as_float(hp & 0xFFFF0000u);
        *dH = hp;
        *dL = packbf2(r1, r0);
    } else {
        *dH = 0u; *dL = 0u;
    }
}

// ---------------------------------------------------------------------------
// z-gen for chunk i into stage st: z[j][d] = x[i,d]*h[j,d], bf16 hi/lo.
static __device__ __forceinline__ void genz(char* smem, int st, int i, int tid) {
    const int tb = tid >> 7, tt = tid & 127;
    const int j  = tt >> 1, d0 = (tt & 1) << 5;
    const float4* xp = (const float4*)((const float*)(smem + XS_OFF)
                                       + tb * 4352 + i * 68 + d0);
    const float4* hp = (const float4*)((const float*)(smem + HS_OFF)
                                       + tb * 4352 + j * 68 + d0);
    char* zh = smem + ZS_OFF + tb * 36864 + st * 18432 + j * 144 + d0 * 2;
    char* zl = zh + 9216;
    #pragma unroll
    for (int s = 0; s < 4; ++s) {
        uint4 H, L;
        #pragma unroll
        for (int p = 0; p < 2; ++p) {
            float4 xv = xp[s * 2 + p];
            float4 hv = hp[s * 2 + p];
            float z0 = xv.x * hv.x, z1 = xv.y * hv.y;
            float z2 = xv.z * hv.z, z3 = xv.w * hv.w;
            uint32_t p01 = packbf2(z1, z0);
            uint32_t p23 = packbf2(z3, z2);
            float r0 = z0 - __uint_as_float(p01 << 16);
            float r1 = z1 - __uint_as_float(p01 & 0xFFFF0000u);
            float r2 = z2 - __uint_as_float(p23 << 16);
            float r3 = z3 - __uint_as_float(p23 & 0xFFFF0000u);
            uint32_t q01 = packbf2(r1, r0);
            uint32_t q23 = packbf2(r3, r2);
            if (p == 0) { H.x = p01; H.y = p23; L.x = q01; L.y = q23; }
            else        { H.z = p01; H.w = p23; L.z = q01; L.w = q23; }
        }
        ((uint4*)zh)[s] = H;
        ((uint4*)zl)[s] = L;
    }
}

// W chunk c (0..127) -> stage st, one cp.async group.
static __device__ __forceinline__ void wfetch(uint32_t sb, int st, int c, int tid) {
    const char* src = (const char*)(&g_Wt[0][0][0][0]) + (size_t)c * 18432;
    uint32_t dst = sb + WS_OFF + st * 18432;
    #pragma unroll 1
    for (int q = tid; q < 1152; q += 256) cpa16(dst + q * 16, src + q * 16);
    asm volatile("cp.async.commit_group;" ::: "memory");
}

// ---------------------------------------------------------------------------
__global__ __launch_bounds__(256, 1) void CIN_52553219834054_kernel(
    const float* __restrict__ x,
    const float* __restrict__ b1, const float* __restrict__ b2,
    const float* __restrict__ Wfc, const float* __restrict__ bfc,
    float* __restrict__ out)
{
    extern __shared__ __align__(16) char smem[];
    const uint32_t sb = s2u(smem);
    const int tid = threadIdx.x, wid = tid >> 5, lane = tid & 31;
    const int bb = wid >> 2, mw = wid & 3;

    // ---- load x -> XS and HS (h0 = x), both batches ----
    {
        const float4* xg = (const float4*)(x + (size_t)blockIdx.x * 8192);
        float* XSf = (float*)(smem + XS_OFF);
        float* HSf = (float*)(smem + HS_OFF);
        #pragma unroll
        for (int t = 0; t < 8; ++t) {
            int q = tid + t * 256;
            int b = q >> 10, rem = q & 1023;
            int i = rem >> 4, d4 = (rem & 15) * 4;
            float4 v = xg[q];
            *(float4*)(XSf + b * 4352 + i * 68 + d4) = v;
            *(float4*)(HSf + b * 4352 + i * 68 + d4) = v;
        }
    }
    wfetch(sb, 0, 0, tid);
    asm volatile("cp.async.wait_group 0;" ::: "memory");
    __syncthreads();
    genz(smem, 0, 0, tid);               // chunk 0
    wfetch(sb, 1, 1, tid);
    __syncthreads();

    const int a_lane = (lane & 15) * 144 + ((lane >> 4) << 4) + mw * 2304;
    const int z_lane = (lane & 15) * 144 + ((lane >> 4) << 4);
    float pool = 0.0f;

    #pragma unroll 1
    for (int l = 0; l < 2; ++l) {
        float acc[8][4];
        #pragma unroll
        for (int nt = 0; nt < 8; ++nt)
            #pragma unroll
            for (int e = 0; e < 4; ++e) acc[nt][e] = 0.0f;

        if (l == 1) {                    // chunk 64 z (new h), stage 0
            genz(smem, 0, 0, tid);
            __syncthreads();
        }

        #pragma unroll 1
        for (int i = 0; i < 64; ++i) {
            const int c = l * 64 + i, st = c & 1;
            const uint32_t wb = sb + WS_OFF + st * 18432;
            const uint32_t zb = sb + ZS_OFF + bb * 36864 + st * 18432;

            #pragma unroll
            for (int kk = 0; kk < 4; ++kk) {
                uint32_t ah[4], al[4];
                LDSM4(ah, wb + a_lane + kk * 32);
                LDSM4(al, wb + 9216 + a_lane + kk * 32);
                #pragma unroll
                for (int np = 0; np < 4; ++np) {
                    uint32_t zh[4], zl[4];
                    const uint32_t za = zb + z_lane + kk * 2304 + np * 32;
                    LDSM4T(zh, za);
                    LDSM4T(zl, za + 9216);
                    MMA(acc[2 * np],     ah, zh[0], zh[1]);
                    MMA(acc[2 * np + 1], ah, zh[2], zh[3]);
                    MMA(acc[2 * np],     ah, zl[0], zl[1]);
                    MMA(acc[2 * np + 1], ah, zl[2], zl[3]);
                    MMA(acc[2 * np],     al, zh[0], zh[1]);
                    MMA(acc[2 * np + 1], al, zh[2], zh[3]);
                }
            }

            if (i < 63) genz(smem, st ^ 1, i + 1, tid);
            asm volatile("cp.async.wait_group 0;" ::: "memory");
            __syncthreads();
            if (c + 2 < 128) wfetch(sb, st, c + 2, tid);
        }

        // ---- epilogue: bias + relu (+ h write at l=0) + weighted pool ----
        {
            const float* bg = l ? b2 : b1;
            const int o_lo = mw * 16 + (lane >> 2);
            const int o_hi = o_lo + 8;
            const int dq = (lane & 3) * 2;
            const float blv = bg[o_lo], bhv = bg[o_hi];
            const float wlv = Wfc[l * 64 + o_lo], whv = Wfc[l * 64 + o_hi];
            float* hsb = (float*)(smem + HS_OFF) + bb * 4352;
            float ps = 0.0f;
            #pragma unroll
            for (int nt = 0; nt < 8; ++nt) {
                const int d = nt * 8 + dq;
                float v0 = fmaxf(acc[nt][0] + blv, 0.0f);
                float v1 = fmaxf(acc[nt][1] + blv, 0.0f);
                float v2 = fmaxf(acc[nt][2] + bhv, 0.0f);
                float v3 = fmaxf(acc[nt][3] + bhv, 0.0f);
                if (l == 0) {
                    *(float2*)(hsb + o_lo * 68 + d) = make_float2(v0, v1);
                    *(float2*)(hsb + o_hi * 68 + d) = make_float2(v2, v3);
                }
                ps += wlv * (v0 + v1) + whv * (v2 + v3);
            }
            pool += ps;
        }
        __syncthreads();                 // h visible before next-layer genz
    }

    // ---- reduce pool per batch, write out ----
    #pragma unroll
    for (int off = 16; off > 0; off >>= 1)
        pool += __shfl_xor_sync(0xffffffffu, pool, off);
    float* pb = (float*)(smem + POOL_OFF);
    if (lane == 0) pb[wid] = pool;
    __syncthreads();
    if (tid < 2) {
        const float* q = pb + tid * 4;
        out[2 * blockIdx.x + tid] = q[0] + q[1] + q[2] + q[3] + bfc[0];
    }
}

// ---------------------------------------------------------------------------
extern "C" void kernel_launch(void* const* d_in, const int* in_sizes, int n_in,
                              void* d_out, int out_size) {
    const float* x   = (const float*)d_in[0];
    const float* W1  = (const float*)d_in[1];
    const float* b1  = (const float*)d_in[2];
    const float* W2  = (const float*)d_in[3];
    const float* b2  = (const float*)d_in[4];
    const float* Wfc = (const float*)d_in[5];
    const float* bfc = (const float*)d_in[6];

    cudaFuncSetAttribute(CIN_52553219834054_kernel,
                         cudaFuncAttributeMaxDynamicSharedMemorySize, SMEM_TOTAL);

    CIN_52553219834054_wsplit<<<1152, 256>>>(W1, W2);
    CIN_52553219834054_kernel<<<512, 256, SMEM_TOTAL>>>(
        x, b1, b2, Wfc, bfc, (float*)d_out);
}

// round 6
// speedup vs baseline: 5.3529x; 1.4446x over previous
#include <cuda_runtime.h>
#include <cuda_bf16.h>
#include <stdint.h>

// ============================================================================
// B=1024, F=64, D=64.
//   layer: h'[o,d] = relu(b[o] + sum_{i,j} W[o,i*64+j] * x[i,d] * h[j,d])
//   out[b] = bfc + sum_o Wfc[o]*sum_d h1 + sum_o Wfc[64+o]*sum_d h2
//
// h-stationary HMMA formulation (mma.sync m16n8k16 bf16->f32):
//   per chunk i:  G = W_i @ h      (B-operand h fragments live in REGISTERS,
//                                   loaded once per layer)
//                 acc[o,d] += x[i,d] * G[o,d]   (exact fp32 FFMA)
// bf16x3 on the GEMM: G = Wh*hh + Wh*hl + Wl*hh.
// Per CTA: 2 batches; 8 warps = 2 batches x 2 m-halves x 2 n-halves (m32n32).
// W hi/lo pre-split + padded (72 bf16 rows) by prologue; streamed cp.async.
// ============================================================================

#define WS_OFF   0            // W stages: 2 x (hi 9216 + lo 9216) = 36864
#define HH_OFF   36864        // h bf16: 2 batches x (hi 9216 + lo 9216)
#define XS_OFF   73728        // x fp32 [b][i*68 + d]  (2 x 17408)
#define POOL_OFF 108544
#define SMEM_TOTAL 108608

// Pre-split, pre-padded W tiles: [l][i][half][o*72 + j] bf16 (j pads zeroed)
__device__ __align__(16) __nv_bfloat16 g_Wt[2][64][2][64 * 72];

// ---------------------------------------------------------------------------
static __device__ __forceinline__ uint32_t s2u(const void* p) {
    uint32_t a;
    asm("{ .reg .u64 t; cvta.to.shared.u64 t, %1; cvt.u32.u64 %0, t; }"
        : "=r"(a) : "l"(p));
    return a;
}
static __device__ __forceinline__ void cpa16(uint32_t dst, const void* src) {
    asm volatile("cp.async.cg.shared.global [%0], [%1], 16;"
                 :: "r"(dst), "l"(src) : "memory");
}
static __device__ __forceinline__ uint32_t packbf2(float hi_el, float lo_el) {
    uint32_t r;   // [31:16]=bf16(hi_el), [15:0]=bf16(lo_el)
    asm("cvt.rn.bf16x2.f32 %0, %1, %2;" : "=r"(r) : "f"(hi_el), "f"(lo_el));
    return r;
}

#define LDSM4(r, addr) \
    asm volatile("ldmatrix.sync.aligned.m8n8.x4.shared.b16 {%0,%1,%2,%3}, [%4];" \
                 : "=r"((r)[0]), "=r"((r)[1]), "=r"((r)[2]), "=r"((r)[3]) \
                 : "r"(addr))
#define LDSM4T(r, addr) \
    asm volatile("ldmatrix.sync.aligned.m8n8.x4.trans.shared.b16 {%0,%1,%2,%3}, [%4];" \
                 : "=r"((r)[0]), "=r"((r)[1]), "=r"((r)[2]), "=r"((r)[3]) \
                 : "r"(addr))
#define MMA(c, a, b0, b1) \
    asm volatile("mma.sync.aligned.m16n8k16.row.col.f32.bf16.bf16.f32 " \
                 "{%0,%1,%2,%3},{%4,%5,%6,%7},{%8,%9},{%0,%1,%2,%3};" \
                 : "+f"((c)[0]), "+f"((c)[1]), "+f"((c)[2]), "+f"((c)[3]) \
                 : "r"((a)[0]), "r"((a)[1]), "r"((a)[2]), "r"((a)[3]), \
                   "r"(b0), "r"(b1))
#define MMAZ(c, a, b0, b1) \
    asm volatile("mma.sync.aligned.m16n8k16.row.col.f32.bf16.bf16.f32 " \
                 "{%0,%1,%2,%3},{%4,%5,%6,%7},{%8,%9},{%10,%10,%10,%10};" \
                 : "=f"((c)[0]), "=f"((c)[1]), "=f"((c)[2]), "=f"((c)[3]) \
                 : "r"((a)[0]), "r"((a)[1]), "r"((a)[2]), "r"((a)[3]), \
                   "r"(b0), "r"(b1), "f"(0.0f))

// ---------------------------------------------------------------------------
// Prologue: split W into bf16 hi/lo, padded rows of 72 bf16 (pads zeroed).
__global__ void CIN_52553219834054_wsplit(const float* __restrict__ W1,
                                          const float* __restrict__ W2) {
    int idx = blockIdx.x * 256 + threadIdx.x;       // < 2*64*64*36 = 294912
    int l  = idx / 147456; int r  = idx - l * 147456;
    int i  = r / 2304;     int r2 = r - i * 2304;
    int o  = r2 / 36;      int jp = r2 - o * 36;
    int j  = jp * 2;
    uint32_t* dH = (uint32_t*)&g_Wt[l][i][0][o * 72 + j];
    uint32_t* dL = (uint32_t*)&g_Wt[l][i][1][o * 72 + j];
    if (j < 64) {
        const float* W = l ? W2 : W1;
        const float* p = W + o * 4096 + i * 64 + j;
        float v0 = p[0], v1 = p[1];
        uint32_t hp = packbf2(v1, v0);
        float r0 = v0 - __uint_as_float(hp << 16);
        float r1 = v1 - __uint_as_float(hp & 0xFFFF0000u);
        *dH = hp;
        *dL = packbf2(r1, r0);
    } else {
        *dH = 0u; *dL = 0u;
    }
}

// W chunk c (0..127) -> stage st, one cp.async group.
static __device__ __forceinline__ void wfetch(uint32_t sb, int st, int c, int tid) {
    const char* src = (const char*)(&g_Wt[0][0][0][0]) + (size_t)c * 18432;
    uint32_t dst = sb + WS_OFF + st * 18432;
    #pragma unroll 1
    for (int q = tid; q < 1152; q += 256) cpa16(dst + q * 16, src + q * 16);
    asm volatile("cp.async.commit_group;" ::: "memory");
}

// ---------------------------------------------------------------------------
__global__ __launch_bounds__(256, 1) void CIN_52553219834054_kernel(
    const float* __restrict__ x,
    const float* __restrict__ b1, const float* __restrict__ b2,
    const float* __restrict__ Wfc, const float* __restrict__ bfc,
    float* __restrict__ out)
{
    extern __shared__ __align__(16) char smem[];
    const uint32_t sb = s2u(smem);
    const int tid = threadIdx.x, wid = tid >> 5, lane = tid & 31;
    const int bb = wid >> 2;          // batch
    const int mh = (wid >> 1) & 1;    // m-half (rows mh*32..+31)
    const int nh = wid & 1;           // n-half (cols nh*32..+31)

    // ---- load x -> XS fp32; also h0 = x as bf16 hi/lo into HH ----
    {
        const float4* xg = (const float4*)(x + (size_t)blockIdx.x * 8192);
        float* XSf = (float*)(smem + XS_OFF);
        #pragma unroll
        for (int t = 0; t < 8; ++t) {
            int q = tid + t * 256;
            int b = q >> 10, rem = q & 1023;
            int i = rem >> 4, d4 = (rem & 15) * 4;
            float4 v = xg[q];
            *(float4*)(XSf + b * 4352 + i * 68 + d4) = v;
            uint32_t hp01 = packbf2(v.y, v.x);
            uint32_t hp23 = packbf2(v.w, v.z);
            float r0 = v.x - __uint_as_float(hp01 << 16);
            float r1 = v.y - __uint_as_float(hp01 & 0xFFFF0000u);
            float r2 = v.z - __uint_as_float(hp23 << 16);
            float r3 = v.w - __uint_as_float(hp23 & 0xFFFF0000u);
            char* hb = smem + HH_OFF + b * 18432;
            *(uint2*)(hb + i * 144 + d4 * 2) = make_uint2(hp01, hp23);
            *(uint2*)(hb + 9216 + i * 144 + d4 * 2) =
                make_uint2(packbf2(r1, r0), packbf2(r3, r2));
        }
    }
    wfetch(sb, 0, 0, tid);
    asm volatile("cp.async.wait_group 0;" ::: "memory");
    __syncthreads();
    wfetch(sb, 1, 1, tid);

    const int zl_lane = (lane & 15) * 144 + ((lane >> 4) << 4);
    const int a_base  = zl_lane + mh * 32 * 144;   // + m*2304 + kk*32
    float pool = 0.0f;

    #pragma unroll 1
    for (int l = 0; l < 2; ++l) {
        // ---- load h fragments (B operand) into registers, once per layer ----
        uint32_t Bh[4][2][4], Bl[4][2][4];
        {
            const uint32_t hbase = sb + HH_OFF + bb * 18432;
            #pragma unroll
            for (int kk = 0; kk < 4; ++kk)
                #pragma unroll
                for (int g = 0; g < 2; ++g) {
                    const uint32_t ad = hbase + zl_lane + kk * 2304
                                      + (nh * 2 + g) * 32;
                    LDSM4T(Bh[kk][g], ad);
                    LDSM4T(Bl[kk][g], ad + 9216);
                }
        }

        float acc[2][4][4];
        #pragma unroll
        for (int m = 0; m < 2; ++m)
            #pragma unroll
            for (int np = 0; np < 4; ++np)
                #pragma unroll
                for (int e = 0; e < 4; ++e) acc[m][np][e] = 0.0f;

        #pragma unroll 1
        for (int i = 0; i < 64; ++i) {
            const int c = l * 64 + i, st = c & 1;
            const uint32_t wb = sb + WS_OFF + st * 18432;

            float G[2][4][4];
            #pragma unroll
            for (int kk = 0; kk < 4; ++kk) {
                uint32_t ah[2][4], al[2][4];
                #pragma unroll
                for (int m = 0; m < 2; ++m) {
                    LDSM4(ah[m], wb + a_base + m * 2304 + kk * 32);
                    LDSM4(al[m], wb + 9216 + a_base + m * 2304 + kk * 32);
                }
                #pragma unroll
                for (int m = 0; m < 2; ++m)
                    #pragma unroll
                    for (int np = 0; np < 4; ++np) {
                        const int g = np >> 1, pr = (np & 1) * 2;
                        const uint32_t b0h = Bh[kk][g][pr], b1h = Bh[kk][g][pr + 1];
                        const uint32_t b0l = Bl[kk][g][pr], b1l = Bl[kk][g][pr + 1];
                        if (kk == 0) { MMAZ(G[m][np], ah[m], b0h, b1h); }
                        else         { MMA (G[m][np], ah[m], b0h, b1h); }
                        MMA(G[m][np], ah[m], b0l, b1l);
                        MMA(G[m][np], al[m], b0h, b1h);
                    }
            }

            // acc += x[i,d] * G   (exact fp32)
            const float* xrow = (const float*)(smem + XS_OFF)
                              + bb * 4352 + i * 68 + nh * 32 + (lane & 3) * 2;
            #pragma unroll
            for (int np = 0; np < 4; ++np) {
                const float2 xv = *(const float2*)(xrow + np * 8);
                #pragma unroll
                for (int m = 0; m < 2; ++m) {
                    acc[m][np][0] += xv.x * G[m][np][0];
                    acc[m][np][1] += xv.y * G[m][np][1];
                    acc[m][np][2] += xv.x * G[m][np][2];
                    acc[m][np][3] += xv.y * G[m][np][3];
                }
            }

            asm volatile("cp.async.wait_group 0;" ::: "memory");
            __syncthreads();
            if (c + 2 < 128) wfetch(sb, st, c + 2, tid);
        }

        // ---- epilogue: bias + relu, pool, write next h (bf16 hi/lo) ----
        {
            const float* bg = l ? b2 : b1;
            const int d0 = nh * 32 + (lane & 3) * 2;
            char* hb = smem + HH_OFF + bb * 18432;
            float ps = 0.0f;
            #pragma unroll
            for (int m = 0; m < 2; ++m) {
                const int o_lo = mh * 32 + m * 16 + (lane >> 2);
                const int o_hi = o_lo + 8;
                const float blv = bg[o_lo], bhv = bg[o_hi];
                const float wlv = Wfc[l * 64 + o_lo], whv = Wfc[l * 64 + o_hi];
                #pragma unroll
                for (int np = 0; np < 4; ++np) {
                    const int d = d0 + np * 8;
                    float v0 = fmaxf(acc[m][np][0] + blv, 0.0f);
                    float v1 = fmaxf(acc[m][np][1] + blv, 0.0f);
                    float v2 = fmaxf(acc[m][np][2] + bhv, 0.0f);
                    float v3 = fmaxf(acc[m][np][3] + bhv, 0.0f);
                    ps += wlv * (v0 + v1) + whv * (v2 + v3);
                    if (l == 0) {
                        uint32_t hpL = packbf2(v1, v0);
                        float q0 = v0 - __uint_as_float(hpL << 16);
                        float q1 = v1 - __uint_as_float(hpL & 0xFFFF0000u);
                        uint32_t hpH = packbf2(v3, v2);
                        float q2 = v2 - __uint_as_float(hpH << 16);
                        float q3 = v3 - __uint_as_float(hpH & 0xFFFF0000u);
                        *(uint32_t*)(hb + o_lo * 144 + d * 2)        = hpL;
                        *(uint32_t*)(hb + 9216 + o_lo * 144 + d * 2) = packbf2(q1, q0);
                        *(uint32_t*)(hb + o_hi * 144 + d * 2)        = hpH;
                        *(uint32_t*)(hb + 9216 + o_hi * 144 + d * 2) = packbf2(q3, q2);
                    }
                }
            }
            pool += ps;
        }
        __syncthreads();   // h visible before next-layer B-frag load
    }

    // ---- reduce pool per batch, write out ----
    #pragma unroll
    for (int off = 16; off > 0; off >>= 1)
        pool += __shfl_xor_sync(0xffffffffu, pool, off);
    float* pb = (float*)(smem + POOL_OFF);
    if (lane == 0) pb[wid] = pool;
    __syncthreads();
    if (tid < 2) {
        const float* q = pb + tid * 4;
        out[2 * blockIdx.x + tid] = q[0] + q[1] + q[2] + q[3] + bfc[0];
    }
}

// ---------------------------------------------------------------------------
extern "C" void kernel_launch(void* const* d_in, const int* in_sizes, int n_in,
                              void* d_out, int out_size) {
    const float* x   = (const float*)d_in[0];
    const float* W1  = (const float*)d_in[1];
    const float* b1  = (const float*)d_in[2];
    const float* W2  = (const float*)d_in[3];
    const float* b2  = (const float*)d_in[4];
    const float* Wfc = (const float*)d_in[5];
    const float* bfc = (const float*)d_in[6];

    cudaFuncSetAttribute(CIN_52553219834054_kernel,
                         cudaFuncAttributeMaxDynamicSharedMemorySize, SMEM_TOTAL);

    CIN_52553219834054_wsplit<<<1152, 256>>>(W1, W2);
    CIN_52553219834054_kernel<<<512, 256, SMEM_TOTAL>>>(
        x, b1, b2, Wfc, bfc, (float*)d_out);
}

// round 7
// speedup vs baseline: 6.6263x; 1.2379x over previous
#include <cuda_runtime.h>
#include <cuda_bf16.h>
#include <stdint.h>

// ============================================================================
// B=1024, F=64, D=64.
//   layer: h'[o,d] = relu(b[o] + sum_{i,j} W[o,i*64+j] * x[i,d] * h[j,d])
//   out[b] = bfc + sum_o Wfc[o]*sum_d h1 + sum_o Wfc[64+o]*sum_d h2
//
// h-stationary HMMA, barrier-free mainloop:
//   per chunk i:  G = W_i @ h   (h B-fragments in registers, per layer)
//                 acc[o,d] += x[i,d] * G[o,d]   (exact fp32)
// bf16x3: G = Wh*hh + Wh*hl + Wl*hh.
// W pre-split into bf16 hi/lo AND pre-arranged in mma-A-fragment register
// order by the prologue -> mainloop A-operands come via coalesced LDG.128
// (L1-cached, shared across warps), double-buffered in registers. No cp.async,
// no ldmatrix for W, no __syncthreads in the mainloop.
// CTA = 1 batch, 128 threads (4 warps = 2 m-halves x 2 n-halves, m32n32),
// 2 CTAs/SM so epilogues/syncs of one CTA overlap MMAs of the other.
// ============================================================================

#define HH_OFF   0            // h bf16: hi 9216 + lo 9216
#define XS_OFF   18432        // x fp32 [i*68 + d] = 17408B
#define POOL_OFF 35840
#define SMEM_TOTAL 35904

// W in fragment order: index ((c*2 + mh)*16 + q)*32 + lane, q = kk*4+half*2+m
// uint4 = the 4 A-fragment regs {a0,a1,a2,a3} for that (chunk, mh, kk, half, m).
__device__ __align__(16) uint4 g_Wf[131072];   // 2 MB

// ---------------------------------------------------------------------------
static __device__ __forceinline__ uint32_t s2u(const void* p) {
    uint32_t a;
    asm("{ .reg .u64 t; cvta.to.shared.u64 t, %1; cvt.u32.u64 %0, t; }"
        : "=r"(a) : "l"(p));
    return a;
}
static __device__ __forceinline__ uint32_t packbf2(float hi_el, float lo_el) {
    uint32_t r;   // [31:16]=bf16(hi_el), [15:0]=bf16(lo_el)
    asm("cvt.rn.bf16x2.f32 %0, %1, %2;" : "=r"(r) : "f"(hi_el), "f"(lo_el));
    return r;
}

#define LDSM4T(r, addr) \
    asm volatile("ldmatrix.sync.aligned.m8n8.x4.trans.shared.b16 {%0,%1,%2,%3}, [%4];" \
                 : "=r"((r)[0]), "=r"((r)[1]), "=r"((r)[2]), "=r"((r)[3]) \
                 : "r"(addr))
#define MMA(c, a, b0, b1) \
    asm volatile("mma.sync.aligned.m16n8k16.row.col.f32.bf16.bf16.f32 " \
                 "{%0,%1,%2,%3},{%4,%5,%6,%7},{%8,%9},{%0,%1,%2,%3};" \
                 : "+f"((c)[0]), "+f"((c)[1]), "+f"((c)[2]), "+f"((c)[3]) \
                 : "r"((a)[0]), "r"((a)[1]), "r"((a)[2]), "r"((a)[3]), \
                   "r"(b0), "r"(b1))
#define MMAZ(c, a, b0, b1) \
    asm volatile("mma.sync.aligned.m16n8k16.row.col.f32.bf16.bf16.f32 " \
                 "{%0,%1,%2,%3},{%4,%5,%6,%7},{%8,%9},{%10,%10,%10,%10};" \
                 : "=f"((c)[0]), "=f"((c)[1]), "=f"((c)[2]), "=f"((c)[3]) \
                 : "r"((a)[0]), "r"((a)[1]), "r"((a)[2]), "r"((a)[3]), \
                   "r"(b0), "r"(b1), "f"(0.0f))

// ---------------------------------------------------------------------------
// Prologue: W -> bf16 hi/lo in mma-A fragment order.
__global__ void CIN_52553219834054_wsplit(const float* __restrict__ W1,
                                          const float* __restrict__ W2) {
    const int idx = blockIdx.x * 256 + threadIdx.x;    // 0..131071
    const int c    = idx >> 10;
    const int rem  = idx & 1023;
    const int mh   = rem >> 9;
    const int rem2 = rem & 511;
    const int q    = rem2 >> 5;
    const int lane = rem2 & 31;
    const int kk = q >> 2, half = (q >> 1) & 1, m = q & 1;
    const int l = c >> 6, i = c & 63;
    const float* __restrict__ W = l ? W2 : W1;
    const int r = lane >> 2, tg = lane & 3;

    uint32_t regs[4];
    #pragma unroll
    for (int e = 0; e < 4; ++e) {
        const int row = mh * 32 + m * 16 + r + (e & 1) * 8;
        const int j   = kk * 16 + tg * 2 + (e >> 1) * 8;
        const float v0 = W[row * 4096 + i * 64 + j];
        const float v1 = W[row * 4096 + i * 64 + j + 1];
        const uint32_t hp = packbf2(v1, v0);
        if (half == 0) {
            regs[e] = hp;
        } else {
            const float r0 = v0 - __uint_as_float(hp << 16);
            const float r1 = v1 - __uint_as_float(hp & 0xFFFF0000u);
            regs[e] = packbf2(r1, r0);
        }
    }
    g_Wf[idx] = make_uint4(regs[0], regs[1], regs[2], regs[3]);
}

// ---------------------------------------------------------------------------
__global__ __launch_bounds__(128, 2) void CIN_52553219834054_kernel(
    const float* __restrict__ x,
    const float* __restrict__ b1, const float* __restrict__ b2,
    const float* __restrict__ Wfc, const float* __restrict__ bfc,
    float* __restrict__ out)
{
    extern __shared__ __align__(16) char smem[];
    const uint32_t sb = s2u(smem);
    const int tid = threadIdx.x, wid = tid >> 5, lane = tid & 31;
    const int mh = wid >> 1;          // m-half (rows mh*32..+31)
    const int nh = wid & 1;           // n-half (cols nh*32..+31)

    // ---- init: x -> XS fp32; h0 = x as bf16 hi/lo ----
    {
        const float4* xg = (const float4*)(x + (size_t)blockIdx.x * 4096);
        float* XSf = (float*)(smem + XS_OFF);
        #pragma unroll
        for (int t = 0; t < 8; ++t) {
            const int q = tid + t * 128;            // 0..1023
            const int i = q >> 4, d4 = (q & 15) * 4;
            const float4 v = xg[q];
            *(float4*)(XSf + i * 68 + d4) = v;
            const uint32_t hp01 = packbf2(v.y, v.x);
            const uint32_t hp23 = packbf2(v.w, v.z);
            const float r0 = v.x - __uint_as_float(hp01 << 16);
            const float r1 = v.y - __uint_as_float(hp01 & 0xFFFF0000u);
            const float r2 = v.z - __uint_as_float(hp23 << 16);
            const float r3 = v.w - __uint_as_float(hp23 & 0xFFFF0000u);
            char* hb = smem + HH_OFF;
            *(uint2*)(hb + i * 144 + d4 * 2) = make_uint2(hp01, hp23);
            *(uint2*)(hb + 9216 + i * 144 + d4 * 2) =
                make_uint2(packbf2(r1, r0), packbf2(r3, r2));
        }
    }
    __syncthreads();

    const int zl_lane = (lane & 15) * 144 + ((lane >> 4) << 4);
    const uint4* __restrict__ wfp = &g_Wf[mh * 512 + lane];  // + c*1024 + kk*128

    // A-fragment double buffer: [buf][0]=hi m0, [1]=hi m1, [2]=lo m0, [3]=lo m1
    uint4 A[2][4];
    {   // preload chunk 0, kk 0
        const uint4* p = wfp;
        A[0][0] = __ldg(p); A[0][1] = __ldg(p + 32);
        A[0][2] = __ldg(p + 64); A[0][3] = __ldg(p + 96);
    }

    float pool = 0.0f;

    #pragma unroll 1
    for (int l = 0; l < 2; ++l) {
        // ---- h B-fragments into registers (once per layer) ----
        uint32_t Bh[4][2][4], Bl[4][2][4];
        {
            const uint32_t hbase = sb + HH_OFF;
            #pragma unroll
            for (int kk = 0; kk < 4; ++kk)
                #pragma unroll
                for (int g = 0; g < 2; ++g) {
                    const uint32_t ad = hbase + zl_lane + kk * 2304
                                      + (nh * 2 + g) * 32;
                    LDSM4T(Bh[kk][g], ad);
                    LDSM4T(Bl[kk][g], ad + 9216);
                }
        }
        __syncthreads();   // all B-frags read before epilogue may rewrite h

        float acc[2][4][4];
        #pragma unroll
        for (int m = 0; m < 2; ++m)
            #pragma unroll
            for (int np = 0; np < 4; ++np)
                #pragma unroll
                for (int e = 0; e < 4; ++e) acc[m][np][e] = 0.0f;

        #pragma unroll 1
        for (int i = 0; i < 64; ++i) {
            const int c = l * 64 + i;
            float G[2][4][4];

            #pragma unroll
            for (int kk = 0; kk < 4; ++kk) {
                // prefetch next (chunk, kk) A-fragments
                {
                    const int nkk = (kk + 1) & 3;
                    const int nc  = (kk == 3) ? c + 1 : c;
                    if (nc < 128) {
                        const uint4* p = wfp + nc * 1024 + nkk * 128;
                        uint4* dst = A[(kk + 1) & 1];
                        dst[0] = __ldg(p);      dst[1] = __ldg(p + 32);
                        dst[2] = __ldg(p + 64); dst[3] = __ldg(p + 96);
                    }
                }
                const uint32_t* Ah[2] = { (const uint32_t*)&A[kk & 1][0],
                                          (const uint32_t*)&A[kk & 1][1] };
                const uint32_t* Al[2] = { (const uint32_t*)&A[kk & 1][2],
                                          (const uint32_t*)&A[kk & 1][3] };
                #pragma unroll
                for (int m = 0; m < 2; ++m)
                    #pragma unroll
                    for (int np = 0; np < 4; ++np) {
                        const int g = np >> 1, pr = (np & 1) * 2;
                        const uint32_t b0h = Bh[kk][g][pr], b1h = Bh[kk][g][pr + 1];
                        const uint32_t b0l = Bl[kk][g][pr], b1l = Bl[kk][g][pr + 1];
                        if (kk == 0) { MMAZ(G[m][np], Ah[m], b0h, b1h); }
                        else         { MMA (G[m][np], Ah[m], b0h, b1h); }
                        MMA(G[m][np], Ah[m], b0l, b1l);
                        MMA(G[m][np], Al[m], b0h, b1h);
                    }
            }

            // acc += x[i,d] * G (exact fp32)
            const float* xrow = (const float*)(smem + XS_OFF)
                              + i * 68 + nh * 32 + (lane & 3) * 2;
            #pragma unroll
            for (int np = 0; np < 4; ++np) {
                const float2 xv = *(const float2*)(xrow + np * 8);
                #pragma unroll
                for (int m = 0; m < 2; ++m) {
                    acc[m][np][0] += xv.x * G[m][np][0];
                    acc[m][np][1] += xv.y * G[m][np][1];
                    acc[m][np][2] += xv.x * G[m][np][2];
                    acc[m][np][3] += xv.y * G[m][np][3];
                }
            }
        }

        // ---- epilogue: bias + relu, pool, write next h (bf16 hi/lo) ----
        {
            const float* bg = l ? b2 : b1;
            const int d0 = nh * 32 + (lane & 3) * 2;
            char* hb = smem + HH_OFF;
            float ps = 0.0f;
            #pragma unroll
            for (int m = 0; m < 2; ++m) {
                const int o_lo = mh * 32 + m * 16 + (lane >> 2);
                const int o_hi = o_lo + 8;
                const float blv = bg[o_lo], bhv = bg[o_hi];
                const float wlv = Wfc[l * 64 + o_lo], whv = Wfc[l * 64 + o_hi];
                #pragma unroll
                for (int np = 0; np < 4; ++np) {
                    const int d = d0 + np * 8;
                    float v0 = fmaxf(acc[m][np][0] + blv, 0.0f);
                    float v1 = fmaxf(acc[m][np][1] + blv, 0.0f);
                    float v2 = fmaxf(acc[m][np][2] + bhv, 0.0f);
                    float v3 = fmaxf(acc[m][np][3] + bhv, 0.0f);
                    ps += wlv * (v0 + v1) + whv * (v2 + v3);
                    if (l == 0) {
                        const uint32_t hpL = packbf2(v1, v0);
                        const float q0 = v0 - __uint_as_float(hpL << 16);
                        const float q1 = v1 - __uint_as_float(hpL & 0xFFFF0000u);
                        const uint32_t hpH = packbf2(v3, v2);
                        const float q2 = v2 - __uint_as_float(hpH << 16);
                        const float q3 = v3 - __uint_as_float(hpH & 0xFFFF0000u);
                        *(uint32_t*)(hb + o_lo * 144 + d * 2)        = hpL;
                        *(uint32_t*)(hb + 9216 + o_lo * 144 + d * 2) = packbf2(q1, q0);
                        *(uint32_t*)(hb + o_hi * 144 + d * 2)        = hpH;
                        *(uint32_t*)(hb + 9216 + o_hi * 144 + d * 2) = packbf2(q3, q2);
                    }
                }
            }
            pool += ps;
        }
        __syncthreads();   // h visible before next-layer B-frag load
    }

    // ---- reduce pool across 4 warps, write out ----
    #pragma unroll
    for (int off = 16; off > 0; off >>= 1)
        pool += __shfl_xor_sync(0xffffffffu, pool, off);
    float* pb = (float*)(smem + POOL_OFF);
    if (lane == 0) pb[wid] = pool;
    __syncthreads();
    if (tid == 0)
        out[blockIdx.x] = pb[0] + pb[1] + pb[2] + pb[3] + bfc[0];
}

// ---------------------------------------------------------------------------
extern "C" void kernel_launch(void* const* d_in, const int* in_sizes, int n_in,
                              void* d_out, int out_size) {
    const float* x   = (const float*)d_in[0];
    const float* W1  = (const float*)d_in[1];
    const float* b1  = (const float*)d_in[2];
    const float* W2  = (const float*)d_in[3];
    const float* b2  = (const float*)d_in[4];
    const float* Wfc = (const float*)d_in[5];
    const float* bfc = (const float*)d_in[6];

    cudaFuncSetAttribute(CIN_52553219834054_kernel,
                         cudaFuncAttributeMaxDynamicSharedMemorySize, SMEM_TOTAL);

    CIN_52553219834054_wsplit<<<512, 256>>>(W1, W2);
    CIN_52553219834054_kernel<<<1024, 128, SMEM_TOTAL>>>(
        x, b1, b2, Wfc, bfc, (float*)d_out);
}